// round 7
// baseline (speedup 1.0000x reference)
#include <cuda_runtime.h>
#include <cstdint>
#include <cstddef>

// Problem constants
#define Bm   64     // batch (GEMM M)
#define Sk   720    // seq len (GEMM K)
#define Cc   321    // channels
#define Pp   336    // pred len (GEMM N)
#define WIN  25
#define HALO 12

// Tiling
#define NT   112    // N per block (336 = 3*112)
#define KT   48     // K tile (720 = 15*48)
#define KEXT (KT + 2*HALO)   // 72
#define THREADS 224          // 16 (tm) x 14 (tn)
#define WLOAD_ITERS ((NT * KEXT) / THREADS)   // 8064/224 = 36 exactly

// smem leading dims
#define SA_LD 68    // A tile [KT][SA_LD] (mult of 4 -> float4 aligned)
#define SW_LD 73    // W ext tiles [NT][SW_LD] (odd -> conflict-free col walks)
#define SB_LD 116   // Beff tile [KT][SB_LD] (even -> 8B-aligned float2 rows)

// +1 row on sBe + slack so the k=KT register prefetch stays in-bounds
#define SMEM_FLOATS (KT*SA_LD + 2*NT*SW_LD + (KT+1)*SB_LD + 16)
#define SMEM_BYTES  (SMEM_FLOATS * 4)

// Scratch: x transposed to [c][b][s] (59.2 MB)
__device__ float g_xT[(size_t)Cc * Bm * Sk];

// ---------------------------------------------------------------------------
// Kernel 1: transpose x [b][s][c] -> g_xT [c][b][s]
// ---------------------------------------------------------------------------
__global__ void transpose_kernel(const float* __restrict__ x) {
    __shared__ float tile[32][33];
    int b  = blockIdx.z;
    int c0 = blockIdx.x * 32;
    int s0 = blockIdx.y * 32;
    int tx = threadIdx.x, ty = threadIdx.y;

    #pragma unroll
    for (int i = 0; i < 4; i++) {
        int s = s0 + ty + 8*i;
        int c = c0 + tx;
        if (s < Sk && c < Cc)
            tile[ty + 8*i][tx] = x[((size_t)b * Sk + s) * Cc + c];
    }
    __syncthreads();
    #pragma unroll
    for (int i = 0; i < 4; i++) {
        int c = c0 + ty + 8*i;
        int s = s0 + tx;
        if (c < Cc && s < Sk)
            g_xT[((size_t)c * Bm + b) * Sk + s] = tile[tx][ty + 8*i];
    }
}

// ---------------------------------------------------------------------------
// Kernel 2: folded GEMM, N-packed f32x2 micro-kernel with register pipelining.
//   out[b,c,p] = sum_s xT[c][b][s] * W_eff[c][p][s] + b_res + b_trend
//   W_eff[p,s] = W_res[p,s] + (1/25)*sum_{t in [s-12,s+12] ∩ [0,Sk)} (W_trd-W_res)[p,t]
// Micro-tile per thread: 4 m-rows x 4 n-PAIRS (n = 2*tn + 28*j), 16 FMA2/k.
// B operands loaded as LDS.64 straight into the packed reg (no movs);
// A duplicated with 4 mov.b64 per k. k+1 operands prefetched into registers.
// ---------------------------------------------------------------------------
__global__ __launch_bounds__(THREADS, 2) void dlinear_gemm(
    const float* __restrict__ Wres, const float* __restrict__ bres,
    const float* __restrict__ Wtrd, const float* __restrict__ btrd,
    float* __restrict__ out)
{
    extern __shared__ float smem[];
    float* sA  = smem;                      // [KT][SA_LD]   x^T tile, [k][m]
    float* sWr = sA  + KT * SA_LD;          // [NT][SW_LD]   W_res extended
    float* sDf = sWr + NT * SW_LD;          // [NT][SW_LD]   W_trd - W_res extended
    float* sBe = sDf + NT * SW_LD;          // [KT(+1)][SB_LD] W_eff tile, [k][n]

    const int c   = blockIdx.y;
    const int n0  = blockIdx.x * NT;
    const int tid = threadIdx.x;
    const int tm  = tid / 14;   // 0..15 -> m base = 4*tm
    const int tn  = tid % 14;   // 0..13 -> n pairs at 2*tn + 28*j

    const float* xT = g_xT + (size_t)c * Bm * Sk;
    const float* wr = Wres + ((size_t)c * Pp + n0) * Sk;
    const float* wt = Wtrd + ((size_t)c * Pp + n0) * Sk;

    // acc[i][j]: packed over n-pair {2tn+28j, 2tn+28j+1}, m = 4tm+i
    unsigned long long acc[4][4];
    #pragma unroll
    for (int i = 0; i < 4; i++)
        #pragma unroll
        for (int j = 0; j < 4; j++) acc[i][j] = 0ULL;

    const float* pA = sA  + tm * 4;
    const char*  pB = (const char*)(sBe + tn * 2);

    for (int k0 = 0; k0 < Sk; k0 += KT) {
        // ---- load A tile: KT*Bm = 3072 floats, coalesced in k ----
        #pragma unroll
        for (int j = 0; j < 14; j++) {
            int idx = tid + THREADS * j;
            if (idx < KT * Bm) {
                int m = idx / KT, k = idx % KT;
                sA[k * SA_LD + m] = xT[(size_t)m * Sk + k0 + k];
            }
        }
        // ---- load extended W tiles: NT*KEXT = 8064 = 224*36 exactly ----
        #pragma unroll
        for (int j = 0; j < WLOAD_ITERS; j++) {
            int idx = tid + THREADS * j;
            int n = idx / KEXT, t = idx % KEXT;
            int s = k0 - HALO + t;
            float a = 0.f, d = 0.f;
            if (s >= 0 && s < Sk) {
                a = wr[(size_t)n * Sk + s];
                d = wt[(size_t)n * Sk + s] - a;
            }
            sWr[n * SW_LD + t] = a;
            sDf[n * SW_LD + t] = d;
        }
        __syncthreads();

        // ---- build W_eff tile: 224 threads = 112 n x 2 k-chunks of 24 ----
        {
            int n  = tid % NT;
            int kb = (tid / NT) * 24;
            const float* dfn = sDf + n * SW_LD;
            float ws = 0.f;
            #pragma unroll
            for (int t = 0; t < WIN; t++) ws += dfn[kb + t];
            #pragma unroll
            for (int i = 0; i < 24; i++) {
                int k = kb + i;
                sBe[k * SB_LD + n] = sWr[n * SW_LD + k + HALO] + ws * (1.0f / 25.0f);
                if (i < 23) ws += dfn[k + WIN] - dfn[k];
            }
        }
        __syncthreads();

        // ---- main FMA loop: register double-buffered ----
        float4 avb[2];
        unsigned long long bvb[2][4];
        avb[0] = *(const float4*)(pA);
        #pragma unroll
        for (int j = 0; j < 4; j++)
            bvb[0][j] = *(const unsigned long long*)(pB + j * (28 * 4));

        #pragma unroll 4
        for (int k = 0; k < KT; k++) {
            const int cur = k & 1, nxt = cur ^ 1;
            // prefetch k+1 (k=KT-1 reads in-bounds padding rows, discarded)
            avb[nxt] = *(const float4*)(pA + (k + 1) * SA_LD);
            const char* pBn = pB + (size_t)(k + 1) * (SB_LD * 4);
            #pragma unroll
            for (int j = 0; j < 4; j++)
                bvb[nxt][j] = *(const unsigned long long*)(pBn + j * (28 * 4));

            // duplicate A lanes
            unsigned long long a0, a1, a2, a3;
            asm("mov.b64 %0, {%1, %1};" : "=l"(a0) : "f"(avb[cur].x));
            asm("mov.b64 %0, {%1, %1};" : "=l"(a1) : "f"(avb[cur].y));
            asm("mov.b64 %0, {%1, %1};" : "=l"(a2) : "f"(avb[cur].z));
            asm("mov.b64 %0, {%1, %1};" : "=l"(a3) : "f"(avb[cur].w));

            #pragma unroll
            for (int j = 0; j < 4; j++) {
                unsigned long long bb = bvb[cur][j];
                asm("fma.rn.f32x2 %0, %1, %2, %0;" : "+l"(acc[0][j]) : "l"(a0), "l"(bb));
                asm("fma.rn.f32x2 %0, %1, %2, %0;" : "+l"(acc[1][j]) : "l"(a1), "l"(bb));
                asm("fma.rn.f32x2 %0, %1, %2, %0;" : "+l"(acc[2][j]) : "l"(a2), "l"(bb));
                asm("fma.rn.f32x2 %0, %1, %2, %0;" : "+l"(acc[3][j]) : "l"(a3), "l"(bb));
            }
        }
        __syncthreads();
    }

    // ---- epilogue: add biases, write out[b][c][p] ----
    #pragma unroll
    for (int j = 0; j < 4; j++) {
        int p = n0 + tn * 2 + j * 28;
        float bias0 = bres[(size_t)c * Pp + p]     + btrd[(size_t)c * Pp + p];
        float bias1 = bres[(size_t)c * Pp + p + 1] + btrd[(size_t)c * Pp + p + 1];
        #pragma unroll
        for (int i = 0; i < 4; i++) {
            float lo, hi;
            asm("mov.b64 {%0, %1}, %2;" : "=f"(lo), "=f"(hi) : "l"(acc[i][j]));
            int m = tm * 4 + i;
            float* o = out + ((size_t)m * Cc + c) * Pp + p;
            o[0] = lo + bias0;
            o[1] = hi + bias1;
        }
    }
}

// ---------------------------------------------------------------------------
extern "C" void kernel_launch(void* const* d_in, const int* in_sizes, int n_in,
                              void* d_out, int out_size) {
    (void)in_sizes; (void)n_in; (void)out_size;
    const float* x    = (const float*)d_in[0];
    const float* Wres = (const float*)d_in[1];
    const float* bres = (const float*)d_in[2];
    const float* Wtrd = (const float*)d_in[3];
    const float* btrd = (const float*)d_in[4];
    float* out = (float*)d_out;

    dim3 tgrid((Cc + 31) / 32, (Sk + 31) / 32, Bm);
    transpose_kernel<<<tgrid, dim3(32, 8)>>>(x);

    cudaFuncSetAttribute(dlinear_gemm,
                         cudaFuncAttributeMaxDynamicSharedMemorySize, SMEM_BYTES);
    dlinear_gemm<<<dim3(Pp / NT, Cc), THREADS, SMEM_BYTES>>>(Wres, bres, Wtrd, btrd, out);
}

// round 10
// speedup vs baseline: 2.5443x; 2.5443x over previous
#include <cuda_runtime.h>
#include <cstdint>
#include <cstddef>

// Problem constants
#define Bm   64     // batch (GEMM M)
#define Sk   720    // seq len (GEMM K)
#define Cc   321    // channels
#define Pp   336    // pred len (GEMM N)
#define WIN  25
#define HALO 12

// Tiling
#define NT   112    // N per block (336 = 3*112)
#define KT   48     // K tile (720 = 15*48)
#define KEXT 72     // KT + 2*HALO
#define NCHUNK 18   // KEXT/4 float4 chunks per W row
#define THREADS 224 // 16 (tm) x 14 (tn)

// smem leading dims (floats). All row strides multiple of 4 -> 16B-aligned
// rows for cp.async 16B chunks.
#define SA_LD 68
#define SW_LD 76
#define SB_LD 116

#define SMEM_FLOATS (KT*SA_LD + 2*NT*SW_LD + (KT+1)*SB_LD + 16)
#define SMEM_BYTES  (SMEM_FLOATS * 4)

// Scratch: x rearranged to [c][s][b] (59.2 MB)
__device__ float g_xT[(size_t)Cc * Sk * Bm];

__device__ __forceinline__ unsigned smem_u32(const void* p) {
    return (unsigned)__cvta_generic_to_shared(p);
}
__device__ __forceinline__ void cp16(unsigned dst, const void* src, unsigned sz) {
    asm volatile("cp.async.ca.shared.global [%0], [%1], 16, %2;"
                 :: "r"(dst), "l"(src), "r"(sz));
}

// ---------------------------------------------------------------------------
// Kernel 1: x [b][s][c] -> g_xT [c][s][b]  (32x32 tiles in (c,b) per s)
// ---------------------------------------------------------------------------
__global__ void transpose_kernel(const float* __restrict__ x) {
    __shared__ float tile[32][33];
    int s  = blockIdx.y;
    int c0 = blockIdx.x * 32;
    int b0 = blockIdx.z * 32;
    int tx = threadIdx.x, ty = threadIdx.y;

    #pragma unroll
    for (int i = 0; i < 4; i++) {
        int b = b0 + ty + 8*i, c = c0 + tx;
        if (c < Cc)
            tile[ty + 8*i][tx] = x[((size_t)b * Sk + s) * Cc + c];
    }
    __syncthreads();
    #pragma unroll
    for (int i = 0; i < 4; i++) {
        int c = c0 + ty + 8*i, b = b0 + tx;
        if (c < Cc)
            g_xT[((size_t)c * Sk + s) * Bm + b] = tile[tx][ty + 8*i];
    }
}

// ---------------------------------------------------------------------------
// Kernel 2: folded GEMM with cp.async tile loads.
//   out[b,c,p] = sum_s xT[c][s][b] * W_eff[c][p][s] + b_res + b_trend
//   W_eff[p,s] = W_res[p,s] + (1/25)*sum_{t in [s-12,s+12] ∩ [0,Sk)} (W_trd-W_res)[p,t]
// ---------------------------------------------------------------------------
__global__ __launch_bounds__(THREADS, 2) void dlinear_gemm(
    const float* __restrict__ Wres, const float* __restrict__ bres,
    const float* __restrict__ Wtrd, const float* __restrict__ btrd,
    float* __restrict__ out)
{
    extern __shared__ float smem[];
    float* sA  = smem;                      // [KT][SA_LD]    x tile, [k][m]
    float* sWr = sA  + KT * SA_LD;          // [NT][SW_LD]    W_res extended (raw)
    float* sWt = sWr + NT * SW_LD;          // [NT][SW_LD]    W_trd extended (raw)
    float* sBe = sWt + NT * SW_LD;          // [KT+1][SB_LD]  W_eff tile, [k][n]

    const int c   = blockIdx.y;
    const int n0  = blockIdx.x * NT;
    const int tid = threadIdx.x;
    const int tm  = tid / 14;   // 0..15 -> m base = 4*tm
    const int tn  = tid % 14;   // 0..13 -> n pairs at 2*tn + 28*j

    const float* xT = g_xT + (size_t)c * Sk * Bm;
    const float* wr = Wres + ((size_t)c * Pp + n0) * Sk;
    const float* wt = Wtrd + ((size_t)c * Pp + n0) * Sk;

    unsigned long long acc[4][4];
    #pragma unroll
    for (int i = 0; i < 4; i++)
        #pragma unroll
        for (int j = 0; j < 4; j++) acc[i][j] = 0ULL;

    const float* pA = sA  + tm * 4;
    const char*  pB = (const char*)(sBe + tn * 2);

    for (int k0 = 0; k0 < Sk; k0 += KT) {
        // ---- A tile via cp.async: KT rows x 16 chunks = 768 chunks ----
        #pragma unroll
        for (int j = 0; j < 4; j++) {
            int idx = tid + THREADS * j;
            if (idx < KT * 16) {
                int k = idx >> 4, ci = idx & 15;
                cp16(smem_u32(sA + k * SA_LD + ci * 4),
                     xT + (size_t)(k0 + k) * Bm + ci * 4, 16u);
            }
        }
        // ---- W ext tiles via cp.async: 2 * NT * NCHUNK = 4032 = 224*18 ----
        #pragma unroll
        for (int j = 0; j < 2 * NCHUNK; j++) {
            int idx = tid + THREADS * j;
            int t   = idx / (NT * NCHUNK);           // 0 = Wres, 1 = Wtrd
            int rem = idx - t * (NT * NCHUNK);
            int n   = rem / NCHUNK, ci = rem % NCHUNK;
            int s0  = k0 - HALO + ci * 4;
            unsigned ok = (s0 >= 0 && s0 <= Sk - 4) ? 16u : 0u;
            int s0c = s0 < 0 ? 0 : (s0 > Sk - 4 ? Sk - 4 : s0);
            const float* src = (t ? wt : wr) + (size_t)n * Sk + s0c;
            float* dst = (t ? sWt : sWr) + n * SW_LD + ci * 4;
            cp16(smem_u32(dst), src, ok);
        }
        asm volatile("cp.async.commit_group;" ::: "memory");
        asm volatile("cp.async.wait_group 0;" ::: "memory");
        __syncthreads();

        // ---- build W_eff: 224 threads = 112 n x 2 chunk-halves of 6 groups ----
        {
            int n  = tid % NT;
            int cb = (tid / NT) * 6;          // chunk base (kb = 4*cb)
            const float4* wr4 = (const float4*)(sWr + n * SW_LD);
            const float4* wt4 = (const float4*)(sWt + n * SW_LD);
            float* beo = sBe + n;
            int kb = cb * 4;

            float4 dbuf[12];
            float cs = 0.f;
            #pragma unroll
            for (int t = 0; t < 6; t++) {
                float4 a = wr4[cb + t], b = wt4[cb + t];
                float4 d = make_float4(b.x - a.x, b.y - a.y, b.z - a.z, b.w - a.w);
                dbuf[t] = d;
                cs += (d.x + d.y) + (d.z + d.w);
            }
            #pragma unroll
            for (int j = 0; j < 6; j++) {
                float4 a  = wr4[cb + j + 6], b = wt4[cb + j + 6];
                float4 dn = make_float4(b.x - a.x, b.y - a.y, b.z - a.z, b.w - a.w);
                float4 wo = wr4[cb + j + 3];   // wr_ext[k+12 .. k+15]
                float4 d0 = dbuf[j];
                float S0 = cs + dn.x;
                float S1 = S0 + dn.y - d0.x;
                float S2 = S1 + dn.z - d0.y;
                float S3 = S2 + dn.w - d0.z;
                int k = kb + 4 * j;
                beo[(k + 0) * SB_LD] = wo.x + S0 * (1.0f / 25.0f);
                beo[(k + 1) * SB_LD] = wo.y + S1 * (1.0f / 25.0f);
                beo[(k + 2) * SB_LD] = wo.z + S2 * (1.0f / 25.0f);
                beo[(k + 3) * SB_LD] = wo.w + S3 * (1.0f / 25.0f);
                cs += ((dn.x + dn.y) + (dn.z + dn.w))
                    - ((d0.x + d0.y) + (d0.z + d0.w));
                dbuf[j + 6] = dn;
            }
        }
        __syncthreads();

        // ---- main FMA loop: register double-buffered, f32x2 packed ----
        float4 avb[2];
        unsigned long long bvb[2][4];
        avb[0] = *(const float4*)(pA);
        #pragma unroll
        for (int j = 0; j < 4; j++)
            bvb[0][j] = *(const unsigned long long*)(pB + j * (28 * 4));

        #pragma unroll 4
        for (int k = 0; k < KT; k++) {
            const int cur = k & 1, nxt = cur ^ 1;
            avb[nxt] = *(const float4*)(pA + (k + 1) * SA_LD);
            const char* pBn = pB + (size_t)(k + 1) * (SB_LD * 4);
            #pragma unroll
            for (int j = 0; j < 4; j++)
                bvb[nxt][j] = *(const unsigned long long*)(pBn + j * (28 * 4));

            unsigned long long a0, a1, a2, a3;
            asm("mov.b64 %0, {%1, %1};" : "=l"(a0) : "f"(avb[cur].x));
            asm("mov.b64 %0, {%1, %1};" : "=l"(a1) : "f"(avb[cur].y));
            asm("mov.b64 %0, {%1, %1};" : "=l"(a2) : "f"(avb[cur].z));
            asm("mov.b64 %0, {%1, %1};" : "=l"(a3) : "f"(avb[cur].w));

            #pragma unroll
            for (int j = 0; j < 4; j++) {
                unsigned long long bb = bvb[cur][j];
                asm("fma.rn.f32x2 %0, %1, %2, %0;" : "+l"(acc[0][j]) : "l"(a0), "l"(bb));
                asm("fma.rn.f32x2 %0, %1, %2, %0;" : "+l"(acc[1][j]) : "l"(a1), "l"(bb));
                asm("fma.rn.f32x2 %0, %1, %2, %0;" : "+l"(acc[2][j]) : "l"(a2), "l"(bb));
                asm("fma.rn.f32x2 %0, %1, %2, %0;" : "+l"(acc[3][j]) : "l"(a3), "l"(bb));
            }
        }
        __syncthreads();
    }

    // ---- epilogue: add biases, write out[b][c][p] ----
    #pragma unroll
    for (int j = 0; j < 4; j++) {
        int p = n0 + tn * 2 + j * 28;
        float bias0 = bres[(size_t)c * Pp + p]     + btrd[(size_t)c * Pp + p];
        float bias1 = bres[(size_t)c * Pp + p + 1] + btrd[(size_t)c * Pp + p + 1];
        #pragma unroll
        for (int i = 0; i < 4; i++) {
            float lo, hi;
            asm("mov.b64 {%0, %1}, %2;" : "=f"(lo), "=f"(hi) : "l"(acc[i][j]));
            int m = tm * 4 + i;
            float* o = out + ((size_t)m * Cc + c) * Pp + p;
            o[0] = lo + bias0;
            o[1] = hi + bias1;
        }
    }
}

// ---------------------------------------------------------------------------
extern "C" void kernel_launch(void* const* d_in, const int* in_sizes, int n_in,
                              void* d_out, int out_size) {
    (void)in_sizes; (void)n_in; (void)out_size;
    const float* x    = (const float*)d_in[0];
    const float* Wres = (const float*)d_in[1];
    const float* bres = (const float*)d_in[2];
    const float* Wtrd = (const float*)d_in[3];
    const float* btrd = (const float*)d_in[4];
    float* out = (float*)d_out;

    transpose_kernel<<<dim3((Cc + 31) / 32, Sk, Bm / 32), dim3(32, 8)>>>(x);

    cudaFuncSetAttribute(dlinear_gemm,
                         cudaFuncAttributeMaxDynamicSharedMemorySize, SMEM_BYTES);
    dlinear_gemm<<<dim3(Pp / NT, Cc), THREADS, SMEM_BYTES>>>(Wres, bres, Wtrd, btrd, out);
}